// round 5
// baseline (speedup 1.0000x reference)
#include <cuda_runtime.h>
#include <math.h>

#define B      4096
#define T      70
#define NF     101
#define NFP    104           // padded K for x@W_k (mult of 8)
#define UNITS  125
#define UP     128           // padded K for h@U / h@Wf (mult of 8)
#define H3     375
#define H3P    384
#define TS     56            // T - LAG
#define GAMMA  28
#define OUT    202
#define KS     (UNITS*OUT)   // 25250
#define NW     (KS+OUT)      // 25452
#define CC     0.5413248546129181f
#define RROWS  28
#define RTH    384
#define MTS    34            // transposed stride: [col][slot], slot-pairs 8B aligned
#define XS     36            // k-stride for X [k][slot]
#define HS     32            // k-stride for H [u][slot]
#define PADR   8             // OOB-safe prefetch pad rows

typedef unsigned long long ull;

// ---------------- duplicated-pair weights in __device__ globals ---------------
__device__ float2 g_Wkd[(NFP + PADR) * H3P];
__device__ float2 g_Ud [(UP  + PADR) * H3P];
__device__ float2 g_Wfd[(size_t)GAMMA * UP * H3P + PADR * H3P];
__device__ float  g_b0p[H3P];
__device__ float  g_b1p[H3P];
__device__ float  g_Wfb[GAMMA * H3P];

// ---------------- helpers -----------------------------------------------------
__device__ __forceinline__ ull pk2(float lo, float hi) {
    ull r; asm("mov.b64 %0, {%1,%2};" : "=l"(r) : "f"(lo), "f"(hi)); return r;
}
__device__ __forceinline__ void fma2(ull& d, ull a, ull b) {
    asm("fma.rn.f32x2 %0, %1, %2, %3;" : "=l"(d) : "l"(a), "l"(b), "l"(d));
}
__device__ __forceinline__ float sigf(float x) {
    return __fdividef(1.f, 1.f + __expf(-x));
}
__device__ __forceinline__ float tanhfast(float x) {
    float e = __expf(-2.f * x);
    return __fdividef(1.f - e, 1.f + e);
}
__device__ __forceinline__ float splus(float x) {
    return fmaxf(x, 0.f) + __logf(1.f + __expf(-fabsf(x)));
}
__device__ __forceinline__ void gbar(int id) {
    asm volatile("bar.sync %0, %1;" :: "r"(id), "r"(192) : "memory");
}

// ---------------- prep kernel -------------------------------------------------
#define R1 (NFP * H3P)
#define R2 (R1 + UP * H3P)
#define R3 (R2 + H3P)
#define R4 (R3 + H3P)
#define R5 (R4 + GAMMA * UP * H3P)
#define R6 (R5 + GAMMA * H3P)

__global__ void prep_kernel(const float* __restrict__ W_k,
                            const float* __restrict__ U,
                            const float* __restrict__ bvec,
                            const float* __restrict__ loc,
                            const float* __restrict__ rho,
                            const float* __restrict__ ew0,
                            const float* __restrict__ ew) {
    int idx = blockIdx.x * blockDim.x + threadIdx.x;
    if (idx < R1) {
        int k = idx / H3P, j = idx - k * H3P;
        float v = (j < H3 && k < NF) ? W_k[k * H3 + j] : 0.f;
        g_Wkd[idx] = make_float2(v, v);
    } else if (idx < R2) {
        int i2 = idx - R1;
        int k = i2 / H3P, j = i2 - k * H3P;
        float v = (j < H3 && k < UNITS) ? U[k * H3 + j] : 0.f;
        g_Ud[i2] = make_float2(v, v);
    } else if (idx < R3) {
        int j = idx - R2;
        g_b0p[j] = (j < H3) ? bvec[j] : 0.f;
    } else if (idx < R4) {
        int j = idx - R3;
        g_b1p[j] = (j < H3) ? bvec[H3 + j] : 0.f;
    } else if (idx < R5) {
        int i2 = idx - R4;
        int g = i2 / (UP * H3P);
        int rem = i2 - g * (UP * H3P);
        int k = rem / H3P, j = rem - k * H3P;
        float v = 0.f;
        if (j < OUT && k < UNITS) {
            int i = k * OUT + j;
            float e = g ? ew[(size_t)(g - 1) * NW + i] : ew0[i];
            v = fmaf(1e-5f + 0.01f * splus(CC + rho[i]), e, loc[i]);
        }
        g_Wfd[i2] = make_float2(v, v);
    } else if (idx < R6) {
        int i2 = idx - R5;
        int g = i2 / H3P, j = i2 - g * H3P;
        float v = 0.f;
        if (j < OUT) {
            int i = KS + j;
            float e = g ? ew[(size_t)(g - 1) * NW + i] : ew0[i];
            v = fmaf(1e-5f + 0.01f * splus(CC + rho[i]), e, loc[i]);
        }
        g_Wfb[i2] = v;
    }
}

// ---------------- 4-k chunk of packed FMAs ------------------------------------
template<int SS>
__device__ __forceinline__ void chunk4(ull (&a)[14], const float* __restrict__ src,
                                       int rb, const ull* w0, const ull* w1) {
#pragma unroll
    for (int c = 0; c < 4; c++) {
        const float* s = src + c * SS + rb;
        ulonglong2 q0 = *(const ulonglong2*)(s);
        ulonglong2 q1 = *(const ulonglong2*)(s + 4);
        ulonglong2 q2 = *(const ulonglong2*)(s + 8);
        ull p6 = *(const ull*)(s + 12);
        ull u0 = w0[c], u1 = w1[c];
        fma2(a[0], q0.x, u0);  fma2(a[1], q0.y, u0);
        fma2(a[2], q1.x, u0);  fma2(a[3], q1.y, u0);
        fma2(a[4], q2.x, u0);  fma2(a[5], q2.y, u0);
        fma2(a[6], p6,  u0);
        fma2(a[7],  q0.x, u1); fma2(a[8],  q0.y, u1);
        fma2(a[9],  q1.x, u1); fma2(a[10], q1.y, u1);
        fma2(a[11], q2.x, u1); fma2(a[12], q2.y, u1);
        fma2(a[13], p6,  u1);
    }
}

// ---------------- tile GEMM: dup-pair weights, packed transposed store --------
// dstT[j*MTS + s] layout; W2 = duplicated pairs [k*H3P + j]
template<int KP, int SS>
__device__ __forceinline__ void gemm_step(const ull* __restrict__ W2,
                                          const float* __restrict__ bias,
                                          const float* __restrict__ src,
                                          float* __restrict__ dstT,
                                          int rb, int j0, int j1) {
    ull a[14];
    {
        float bb0 = bias[j0], bb1 = bias[j1];
        ull pb0 = pk2(bb0, bb0), pb1 = pk2(bb1, bb1);
#pragma unroll
        for (int i = 0; i < 7; i++) { a[i] = pb0; a[7 + i] = pb1; }
    }
    ull wa0[4], wb0[4], wa1[4], wb1[4];
#pragma unroll
    for (int c = 0; c < 4; c++) {
        wa0[c] = W2[c * H3P + j0];       wb0[c] = W2[c * H3P + j1];
        wa1[c] = W2[(4 + c) * H3P + j0]; wb1[c] = W2[(4 + c) * H3P + j1];
    }
#pragma unroll 1
    for (int kc = 0; kc < KP; kc += 8) {
        const ull* Wn = W2 + (size_t)(kc + 8) * H3P;
        chunk4<SS>(a, src + kc * SS, rb, wa0, wb0);
#pragma unroll
        for (int c = 0; c < 4; c++) { wa0[c] = Wn[c * H3P + j0]; wb0[c] = Wn[c * H3P + j1]; }
        chunk4<SS>(a, src + (kc + 4) * SS, rb, wa1, wb1);
#pragma unroll
        for (int c = 0; c < 4; c++) { wa1[c] = Wn[(4 + c) * H3P + j0]; wb1[c] = Wn[(4 + c) * H3P + j1]; }
    }
#pragma unroll
    for (int i = 0; i < 7; i++) {
        *(ull*)(dstT + j0 * MTS + rb + 2 * i) = a[i];
        *(ull*)(dstT + j1 * MTS + rb + 2 * i) = a[7 + i];
    }
}

// ---------------- main persistent recurrence ----------------------------------
#define SM_H    0
#define SM_MXT  (UP * HS)                    // 4096
#define SM_MIT  (SM_MXT + H3P * MTS)         // + 13056
#define SM_X    (SM_MIT + H3P * MTS)         // + 13056
#define SM_TOT  (SM_X + NFP * XS)            // + 3744 = 33952 floats = 135808 B

extern __shared__ float smem[];

__global__ __launch_bounds__(RTH, 1) void rec_kernel(
    const float* __restrict__ inp, const float* __restrict__ eps_s,
    float* __restrict__ out)
{
    float* sH   = smem + SM_H;
    float* sMXT = smem + SM_MXT;
    float* sMIT = smem + SM_MIT;
    float* sX   = smem + SM_X;

    int b0 = blockIdx.x * RROWS;
    int R = min(RROWS, B - b0);
    int tid = threadIdx.x;
    int grp = (tid >= 192);
    int rb  = grp ? 16 : 0;
    int tg  = tid - (grp ? 192 : 0);      // 0..191 within group
    int j0  = tg;
    int j1  = tg + 192;
    int bar = 1 + grp;
    int Rg  = min(14, max(0, R - 14 * grp));   // rows this group owns
    int rowg = b0 + 14 * grp;                   // first global row of group

    const ull* Wk2 = (const ull*)g_Wkd;
    const ull* U2  = (const ull*)g_Ud;

    for (int i = tid; i < UP * HS; i += RTH)  sH[i] = 0.f;
    for (int i = tid; i < NFP * XS; i += RTH) sX[i] = 0.f;

    float xr[8];
    // preload x(t=0) for own group's rows
    {
        int i = 0;
        for (int idx = tg; idx < Rg * NF; idx += 192, i++)
            xr[i] = inp[((size_t)(rowg + idx / NF) * T + 0) * NF + (idx % NF)];
    }
    __syncthreads();
    {
        int i = 0;
        for (int idx = tg; idx < Rg * NF; idx += 192, i++) {
            int r = idx / NF, f = idx - r * NF;
            sX[f * XS + rb + r] = xr[i];
        }
    }
    gbar(bar);

    // ---------- phase 1: 56 warmup GRU steps ----------
    for (int t = 0; t < TS; t++) {
        if (t + 1 < TS) {
            int i = 0;
            for (int idx = tg; idx < Rg * NF; idx += 192, i++)
                xr[i] = inp[((size_t)(rowg + idx / NF) * T + (t + 1)) * NF + (idx % NF)];
        }
        gemm_step<NFP, XS>(Wk2, g_b0p, sX, sMXT, rb, j0, j1);
        gemm_step<UP,  HS>(U2,  g_b1p, sH, sMIT, rb, j0, j1);
        gbar(bar);
        // GRU elementwise (group-local slots)
        for (int idx = tg; idx < Rg * UNITS; idx += 192) {
            int r = idx / UNITS, u = idx - r * UNITS;
            int s = rb + r;
            float z  = sigf(sMXT[u * MTS + s] + sMIT[u * MTS + s]);
            float rg = sigf(sMXT[(UNITS + u) * MTS + s] + sMIT[(UNITS + u) * MTS + s]);
            float hh = tanhfast(fmaf(rg, sMIT[(2 * UNITS + u) * MTS + s],
                                     sMXT[(2 * UNITS + u) * MTS + s]));
            float ho = sH[u * HS + s];
            sH[u * HS + s] = fmaf(z, ho - hh, hh);
        }
        if (t + 1 < TS) {
            int i = 0;
            for (int idx = tg; idx < Rg * NF; idx += 192, i++) {
                int r = idx / NF, f = idx - r * NF;
                sX[f * XS + rb + r] = xr[i];
            }
        }
        gbar(bar);
    }

    // ---------- phase 2: 28 dense draws + 27 feedback GRU steps ----------
    for (int g = 0; g < GAMMA; g++) {
        if (g < GAMMA - 1) {
            int i = 0;
            for (int idx = tg; idx < Rg * NF; idx += 192, i++)
                xr[i] = eps_s[((size_t)g * B + rowg + idx / NF) * NF + (idx % NF)];
        }
        // y = h @ Wf[g] + bf[g] -> sMIT
        gemm_step<UP, HS>((const ull*)(g_Wfd + (size_t)g * UP * H3P),
                          g_Wfb + g * H3P, sH, sMIT, rb, j0, j1);
        gbar(bar);
        // dist params -> output + feedback x
        {
            int i = 0;
            for (int idx = tg; idx < Rg * NF; idx += 192, i++) {
                int r = idx / NF, f = idx - r * NF;
                int s = rb + r;
                float loc = sMIT[f * MTS + s];
                float sc  = 1e-5f + 0.05f * splus(CC + sMIT[(NF + f) * MTS + s]);
                size_t ob = ((size_t)(rowg + r) * GAMMA + g) * OUT;
                out[ob + f]      = loc;
                out[ob + NF + f] = sc;
                if (g < GAMMA - 1) sX[f * XS + s] = fmaf(sc, xr[i], loc);
            }
        }
        gbar(bar);
        if (g == GAMMA - 1) break;

        gemm_step<NFP, XS>(Wk2, g_b0p, sX, sMXT, rb, j0, j1);
        gemm_step<UP,  HS>(U2,  g_b1p, sH, sMIT, rb, j0, j1);
        gbar(bar);
        for (int idx = tg; idx < Rg * UNITS; idx += 192) {
            int r = idx / UNITS, u = idx - r * UNITS;
            int s = rb + r;
            float z  = sigf(sMXT[u * MTS + s] + sMIT[u * MTS + s]);
            float rg = sigf(sMXT[(UNITS + u) * MTS + s] + sMIT[(UNITS + u) * MTS + s]);
            float hh = tanhfast(fmaf(rg, sMIT[(2 * UNITS + u) * MTS + s],
                                     sMXT[(2 * UNITS + u) * MTS + s]));
            float ho = sH[u * HS + s];
            sH[u * HS + s] = fmaf(z, ho - hh, hh);
        }
        gbar(bar);
    }
}

// ---------------- launch ------------------------------------------------------
extern "C" void kernel_launch(void* const* d_in, const int* in_sizes, int n_in,
                              void* d_out, int out_size) {
    const float* inputs = (const float*)d_in[0];
    const float* W_k    = (const float*)d_in[1];
    const float* U      = (const float*)d_in[2];
    const float* b      = (const float*)d_in[3];
    const float* dv_loc = (const float*)d_in[4];
    const float* dv_rho = (const float*)d_in[5];
    const float* eps_w0 = (const float*)d_in[6];
    const float* eps_w  = (const float*)d_in[7];
    const float* eps_s  = (const float*)d_in[8];
    float* out = (float*)d_out;

    prep_kernel<<<(R6 + 255) / 256, 256>>>(W_k, U, b, dv_loc, dv_rho, eps_w0, eps_w);

    cudaFuncSetAttribute(rec_kernel, cudaFuncAttributeMaxDynamicSharedMemorySize,
                         SM_TOT * (int)sizeof(float));
    rec_kernel<<<(B + RROWS - 1) / RROWS, RTH, SM_TOT * sizeof(float)>>>(
        inputs, eps_s, out);
}